// round 8
// baseline (speedup 1.0000x reference)
#include <cuda_runtime.h>
#include <math.h>

// DDSL spec: B=2, NV=NE=512, RES=(128,128) -> freq grid 128 x 65, J=2.
// ky-sweep phase recurrence: block = (kx-pair, 13-ky chunk, batch); thread
// owns 2 ring-adjacent edges (3 vertices). Stepping ky rotates each vertex
// phase by fixed 2*pi*y (4 packed FMA) -> no sincos in the hot loop; only
// rcp MUFU per eval. Packed over (kx, kx+1) via f32x2.
// R8: full unroll, 1-level shfl pre-reduce (smem 28.7KB), 5 blocks/SM.

#define NVV    512
#define NEE    512
#define FXX    128
#define FY2    65
#define KXP    64          // kx-pairs
#define CHUNK  13
#define NCHUNK 5           // 5*13 = 65 ky values
#define BLOCK  256
#define ROWW   128         // partials per step after 1-level warp reduce

#define NPART      (CHUNK * ROWW)
#define SMEM_BYTES (2 * NPART * 8 + NEE * 4)   // 26624 + 2048 = 28672

typedef unsigned long long u64;

__device__ __forceinline__ u64 pk2(float a, float b) {
    u64 r; asm("mov.b64 %0, {%1, %2};" : "=l"(r) : "f"(a), "f"(b)); return r;
}
__device__ __forceinline__ void upk(u64 v, float& a, float& b) {
    asm("mov.b64 {%0, %1}, %2;" : "=f"(a), "=f"(b) : "l"(v));
}
__device__ __forceinline__ u64 f2fma(u64 a, u64 b, u64 c) {
    u64 d; asm("fma.rn.f32x2 %0, %1, %2, %3;" : "=l"(d) : "l"(a), "l"(b), "l"(c)); return d;
}
__device__ __forceinline__ u64 f2add(u64 a, u64 b) {
    u64 d; asm("add.rn.f32x2 %0, %1, %2;" : "=l"(d) : "l"(a), "l"(b)); return d;
}
__device__ __forceinline__ u64 f2mul(u64 a, u64 b) {
    u64 d; asm("mul.rn.f32x2 %0, %1, %2;" : "=l"(d) : "l"(a), "l"(b)); return d;
}

__device__ __forceinline__ float fracr(float t) {
    const float MAGIC = 12582912.0f;  // 1.5 * 2^23
    float g = __fadd_rn(t, MAGIC);
    float r = __fadd_rn(g, -MAGIC);
    return t - r;
}

// init vertex state at ky0. NOTE: __sincosf writes SIN first, COS second.
#define INITV(X, Y, T, C, S, CW, SW, YS)                                   \
    {                                                                      \
        float tl = fmaf((Y), fky0, (X) * fkx);                             \
        float th = tl + (X);                                               \
        float sl, cl, sh, chh;                                             \
        __sincosf(fracr(tl) * TWO_PI, &sl, &cl);                           \
        __sincosf(fracr(th) * TWO_PI, &sh, &chh);                          \
        T = pk2(tl, th); C = pk2(cl, chh); S = pk2(sl, sh);                \
        float cy, syv;                                                     \
        __sincosf(fracr(Y) * TWO_PI, &syv, &cy);  /* sin->syv, cos->cy */  \
        CW = pk2(cy, cy); SW = pk2(syv, syv); YS = pk2((Y), (Y));          \
    }

// edge contribution: numR = dt + ca*tb - cb*ta ; numI2 = sa*tb - sb*ta
// rc = cd / (ta*tb*dt) guarded; acc{R,I} {=, +=} num * rc
#define EVAL(TA, CA, SA, TB, CB, SB, CD, AR, AI, FIRST)                    \
    {                                                                      \
        u64 dt  = f2fma(TB, NEG1, TA);                                     \
        u64 den = f2mul(f2mul(TA, TB), dt);                                \
        u64 nta = f2mul(TA, NEG1);                                         \
        u64 nr  = f2fma(CB, nta, f2fma(CA, TB, dt));                       \
        u64 ni  = f2fma(SB, nta, f2mul(SA, TB));                           \
        float dlo, dhi; upk(den, dlo, dhi);                                \
        float rlo = (dlo != 0.0f) ? __fdividef(CD, dlo) : 0.0f;            \
        float rhi = (dhi != 0.0f) ? __fdividef(CD, dhi) : 0.0f;            \
        u64 rc = pk2(rlo, rhi);                                            \
        if (FIRST) { AR = f2mul(nr, rc); AI = f2mul(ni, rc); }             \
        else       { AR = f2fma(nr, rc, AR); AI = f2fma(ni, rc, AI); }     \
    }

// rotate phase by 2*pi*y and advance t by y
#define ROT(T, C, S, CW, SW, YS)                                           \
    {                                                                      \
        u64 ms = f2mul(S, SW);                                             \
        u64 nc = f2fma(ms, NEG1, f2mul(C, CW));                            \
        u64 ns = f2fma(C, SW, f2mul(S, CW));                               \
        C = nc; S = ns; T = f2add(T, YS);                                  \
    }

__global__ __launch_bounds__(BLOCK, 5)
void ddsl_spec_kernel(const float* __restrict__ V,
                      const int*   __restrict__ E,
                      const float* __restrict__ D,
                      float*       __restrict__ out)
{
    extern __shared__ char smraw[];
    u64*   sRbuf = (u64*)smraw;             // [CHUNK*ROWW]
    u64*   sIbuf = sRbuf + NPART;           // [CHUNK*ROWW]
    float* scd   = (float*)(sIbuf + NPART); // [NEE]
    float* sx    = (float*)smraw;           // staging, overlaps sRbuf
    float* sy    = sx + NVV + 1;

    const int tid  = threadIdx.x;
    const int wid  = tid >> 5;
    const int lane = tid & 31;
    const int kxp  = blockIdx.x;
    const int ck   = blockIdx.y;
    const int b    = blockIdx.z;

    // ---- stage ring vertices + C*D ----
    for (int e = tid; e < NEE; e += BLOCK) {
        int i0 = E[(b * NEE + e) * 2 + 0];
        int i1 = E[(b * NEE + e) * 2 + 1];
        float ax = V[(b * NVV + i0) * 2 + 0];
        float ay = V[(b * NVV + i0) * 2 + 1];
        float bx = V[(b * NVV + i1) * 2 + 0];
        float by = V[(b * NVV + i1) * 2 + 1];
        sx[e] = ax; sy[e] = ay;
        scd[e] = (ax * by - ay * bx) * D[b * NEE + e];
        if (e == 0) { sx[NVV] = ax; sy[NVV] = ay; }   // ring wrap dup
    }
    __syncthreads();

    const int vv = 2 * tid;
    const float x0 = sx[vv],     y0 = sy[vv];
    const float x1 = sx[vv + 1], y1 = sy[vv + 1];
    const float x2 = sx[vv + 2], y2 = sy[vv + 2];
    const float cd0 = scd[vv], cd1 = scd[vv + 1];
    __syncthreads();   // staging consumed; sRbuf/sIbuf free to write

    const int fx0 = 2 * kxp;
    const int kx0 = (fx0 < FXX / 2) ? fx0 : fx0 - FXX;
    const float fkx  = (float)kx0;
    const int ky0 = ck * CHUNK;
    const float fky0 = (float)ky0;
    const float TWO_PI = 6.28318530717958647692f;
    const u64 NEG1 = pk2(-1.0f, -1.0f);

    u64 T0, C0, S0, CW0, SW0, YS0;
    u64 T1, C1, S1, CW1, SW1, YS1;
    u64 T2, C2, S2, CW2, SW2, YS2;
    INITV(x0, y0, T0, C0, S0, CW0, SW0, YS0);
    INITV(x1, y1, T1, C1, S1, CW1, SW1, YS1);
    INITV(x2, y2, T2, C2, S2, CW2, SW2, YS2);

    const int slot = wid * 16 + (lane & 15);

#pragma unroll
    for (int st = 0; st < CHUNK; ++st) {
        u64 aR, aI;
        EVAL(T0, C0, S0, T1, C1, S1, cd0, aR, aI, 1);
        EVAL(T1, C1, S1, T2, C2, S2, cd1, aR, aI, 0);
        // 1-level pre-reduce: lane L holds v[L] + v[L+16] for L < 16
        aR = f2add(aR, __shfl_down_sync(0xFFFFFFFFu, aR, 16));
        aI = f2add(aI, __shfl_down_sync(0xFFFFFFFFu, aI, 16));
        if (lane < 16) {
            sRbuf[st * ROWW + slot] = aR;
            sIbuf[st * ROWW + slot] = aI;
        }
        if (st < CHUNK - 1) {
            ROT(T0, C0, S0, CW0, SW0, YS0);
            ROT(T1, C1, S1, CW1, SW1, YS1);
            ROT(T2, C2, S2, CW2, SW2, YS2);
        }
    }
    __syncthreads();

    // ---- final reduction: 128 partials per (step, kx-slot) ----
    const float SCALE = (float)(-16384.0 / (4.0 * 3.14159265358979323846
                                                * 3.14159265358979323846));
    for (int st = wid; st < CHUNK; st += 8) {
        const u64* rR = &sRbuf[st * ROWW];
        const u64* rI = &sIbuf[st * ROWW];
        u64 aR = f2add(f2add(rR[lane],      rR[lane + 32]),
                       f2add(rR[lane + 64], rR[lane + 96]));
        u64 aI = f2add(f2add(rI[lane],      rI[lane + 32]),
                       f2add(rI[lane + 64], rI[lane + 96]));
#pragma unroll
        for (int off = 16; off > 0; off >>= 1) {
            aR = f2add(aR, __shfl_down_sync(0xFFFFFFFFu, aR, off));
            aI = f2add(aI, __shfl_down_sync(0xFFFFFFFFu, aI, off));
        }
        if (lane == 0) {
            float Rl, Rh, Il, Ih;
            upk(aR, Rl, Rh); upk(aI, Il, Ih);
            float oRl =  SCALE * Rl, oRh =  SCALE * Rh;
            float oIl = -SCALE * Il, oIh = -SCALE * Ih;   // aI held -Im
            int fy = ky0 + st;
            if (kxp == 0 && fy == 0) {
                // DC: F[:,0,0,:,:] = 8192*sum(C*D) in BOTH re and im
                float ssum = 0.0f;
                for (int e = 0; e < NEE; ++e) ssum += scd[e];
                oRl = 8192.0f * ssum;
                oIl = oRl;
            }
            int base = ((b * FXX + fx0) * FY2 + fy) * 2;
            out[base + 0] = oRl;
            out[base + 1] = oIl;
            out[base + 2 * FY2 + 0] = oRh;   // fx0 + 1
            out[base + 2 * FY2 + 1] = oIh;
        }
    }
}

extern "C" void kernel_launch(void* const* d_in, const int* in_sizes, int n_in,
                              void* d_out, int out_size)
{
    const float* V = (const float*)d_in[0];
    const int*   E = (const int*)  d_in[1];
    const float* D = (const float*)d_in[2];
    float* out = (float*)d_out;

    const int B = in_sizes[0] / (NVV * 2);   // 2
    cudaFuncSetAttribute(ddsl_spec_kernel,
                         cudaFuncAttributeMaxDynamicSharedMemorySize, SMEM_BYTES);
    dim3 grid(KXP, NCHUNK, B);               // (64, 5, 2) = 640 blocks
    ddsl_spec_kernel<<<grid, BLOCK, SMEM_BYTES>>>(V, E, D, out);
}

// round 10
// speedup vs baseline: 1.0057x; 1.0057x over previous
#include <cuda_runtime.h>
#include <math.h>

// DDSL spec: B=2, NV=NE=512, RES=(128,128) -> freq grid 128 x 65, J=2.
// ky-sweep phase recurrence: block = (kx-pair, 17-ky chunk, batch); thread
// owns 2 ring-adjacent edges (3 vertices). Stepping ky rotates each vertex
// phase by fixed 2*pi*y (packed FMA) -> no sincos in hot loop; ONE rcp MUFU
// per edge-eval via product-reciprocal. The only systematic denom==0 is the
// lo half at k=(0,0): sanitize dlo (FSEL) so the hi half stays exact and the
// junk lo value lands only in the DC slot, which is overwritten.
// R10: 512 blocks = single co-resident wave (<=592), CHUNK=17.

#define NVV    512
#define NEE    512
#define FXX    128
#define FY2    65
#define KXP    64          // kx-pairs
#define CHUNK  17
#define NCHUNK 4           // 4*17 = 68 >= 65 ky values (tail rows skipped)
#define BLOCK  256
#define ROWW   128         // partials per step after 1-level warp reduce

#define NPART      (CHUNK * ROWW)
#define SMEM_BYTES (2 * NPART * 8 + NEE * 4)   // 34816 + 2048 = 36864

typedef unsigned long long u64;

__device__ __forceinline__ u64 pk2(float a, float b) {
    u64 r; asm("mov.b64 %0, {%1, %2};" : "=l"(r) : "f"(a), "f"(b)); return r;
}
__device__ __forceinline__ void upk(u64 v, float& a, float& b) {
    asm("mov.b64 {%0, %1}, %2;" : "=f"(a), "=f"(b) : "l"(v));
}
__device__ __forceinline__ u64 f2fma(u64 a, u64 b, u64 c) {
    u64 d; asm("fma.rn.f32x2 %0, %1, %2, %3;" : "=l"(d) : "l"(a), "l"(b), "l"(c)); return d;
}
__device__ __forceinline__ u64 f2add(u64 a, u64 b) {
    u64 d; asm("add.rn.f32x2 %0, %1, %2;" : "=l"(d) : "l"(a), "l"(b)); return d;
}
__device__ __forceinline__ u64 f2mul(u64 a, u64 b) {
    u64 d; asm("mul.rn.f32x2 %0, %1, %2;" : "=l"(d) : "l"(a), "l"(b)); return d;
}

__device__ __forceinline__ float fracr(float t) {
    const float MAGIC = 12582912.0f;  // 1.5 * 2^23
    float g = __fadd_rn(t, MAGIC);
    float r = __fadd_rn(g, -MAGIC);
    return t - r;
}

// init vertex state at ky0. NOTE: __sincosf writes SIN first, COS second.
#define INITV(X, Y, T, C, S, CW, SW, YS)                                   \
    {                                                                      \
        float tl = fmaf((Y), fky0, (X) * fkx);                             \
        float th = tl + (X);                                               \
        float sl, cl, sh, chh;                                             \
        __sincosf(fracr(tl) * TWO_PI, &sl, &cl);                           \
        __sincosf(fracr(th) * TWO_PI, &sh, &chh);                          \
        T = pk2(tl, th); C = pk2(cl, chh); S = pk2(sl, sh);                \
        float cy, syv;                                                     \
        __sincosf(fracr(Y) * TWO_PI, &syv, &cy);  /* sin->syv, cos->cy */  \
        CW = pk2(cy, cy); SW = pk2(syv, syv); YS = pk2((Y), (Y));          \
    }

// edge contribution: numR = dt + ca*tb - cb*ta ; numI2 = sa*tb - sb*ta
// rc = cd / (ta*tb*dt) via ONE rcp of the (sanitized) lo*hi product:
//   dlo' = (dlo==0 ? 1 : dlo); rp = cd/(dlo'*dhi); rlo = rp*dhi; rhi = rp*dlo'.
#define EVAL(TA, CA, SA, TB, CB, SB, CD, AR, AI, FIRST)                    \
    {                                                                      \
        u64 dt  = f2fma(TB, NEG1, TA);                                     \
        u64 den = f2mul(f2mul(TA, TB), dt);                                \
        u64 nta = f2mul(TA, NEG1);                                         \
        u64 nr  = f2fma(CB, nta, f2fma(CA, TB, dt));                       \
        u64 ni  = f2fma(SB, nta, f2mul(SA, TB));                           \
        float dlo, dhi; upk(den, dlo, dhi);                                \
        dlo = (dlo == 0.0f) ? 1.0f : dlo;                                  \
        float rp  = __fdividef(CD, dlo * dhi);                             \
        float rlo = rp * dhi;                                              \
        float rhi = rp * dlo;                                              \
        u64 rc = pk2(rlo, rhi);                                            \
        if (FIRST) { AR = f2mul(nr, rc); AI = f2mul(ni, rc); }             \
        else       { AR = f2fma(nr, rc, AR); AI = f2fma(ni, rc, AI); }     \
    }

// rotate phase by 2*pi*y and advance t by y
#define ROT(T, C, S, CW, SW, YS)                                           \
    {                                                                      \
        u64 ms = f2mul(S, SW);                                             \
        u64 nc = f2fma(ms, NEG1, f2mul(C, CW));                            \
        u64 ns = f2fma(C, SW, f2mul(S, CW));                               \
        C = nc; S = ns; T = f2add(T, YS);                                  \
    }

__global__ __launch_bounds__(BLOCK, 4)
void ddsl_spec_kernel(const float* __restrict__ V,
                      const int*   __restrict__ E,
                      const float* __restrict__ D,
                      float*       __restrict__ out)
{
    extern __shared__ char smraw[];
    u64*   sRbuf = (u64*)smraw;             // [CHUNK*ROWW]
    u64*   sIbuf = sRbuf + NPART;           // [CHUNK*ROWW]
    float* scd   = (float*)(sIbuf + NPART); // [NEE]
    float* sx    = (float*)smraw;           // staging, overlaps sRbuf
    float* sy    = sx + NVV + 1;

    const int tid  = threadIdx.x;
    const int wid  = tid >> 5;
    const int lane = tid & 31;
    const int kxp  = blockIdx.x;
    const int ck   = blockIdx.y;
    const int b    = blockIdx.z;

    // ---- stage ring vertices + C*D ----
    for (int e = tid; e < NEE; e += BLOCK) {
        int i0 = E[(b * NEE + e) * 2 + 0];
        int i1 = E[(b * NEE + e) * 2 + 1];
        float ax = V[(b * NVV + i0) * 2 + 0];
        float ay = V[(b * NVV + i0) * 2 + 1];
        float bx = V[(b * NVV + i1) * 2 + 0];
        float by = V[(b * NVV + i1) * 2 + 1];
        sx[e] = ax; sy[e] = ay;
        scd[e] = (ax * by - ay * bx) * D[b * NEE + e];
        if (e == 0) { sx[NVV] = ax; sy[NVV] = ay; }   // ring wrap dup
    }
    __syncthreads();

    const int vv = 2 * tid;
    const float x0 = sx[vv],     y0 = sy[vv];
    const float x1 = sx[vv + 1], y1 = sy[vv + 1];
    const float x2 = sx[vv + 2], y2 = sy[vv + 2];
    const float cd0 = scd[vv], cd1 = scd[vv + 1];
    __syncthreads();   // staging consumed; sRbuf/sIbuf free to write

    const int fx0 = 2 * kxp;
    const int kx0 = (fx0 < FXX / 2) ? fx0 : fx0 - FXX;
    const float fkx  = (float)kx0;
    const int ky0 = ck * CHUNK;
    const float fky0 = (float)ky0;
    const float TWO_PI = 6.28318530717958647692f;
    const u64 NEG1 = pk2(-1.0f, -1.0f);

    u64 T0, C0, S0, CW0, SW0, YS0;
    u64 T1, C1, S1, CW1, SW1, YS1;
    u64 T2, C2, S2, CW2, SW2, YS2;
    INITV(x0, y0, T0, C0, S0, CW0, SW0, YS0);
    INITV(x1, y1, T1, C1, S1, CW1, SW1, YS1);
    INITV(x2, y2, T2, C2, S2, CW2, SW2, YS2);

    const int slot = wid * 16 + (lane & 15);

#pragma unroll
    for (int st = 0; st < CHUNK; ++st) {
        u64 aR, aI;
        EVAL(T0, C0, S0, T1, C1, S1, cd0, aR, aI, 1);
        EVAL(T1, C1, S1, T2, C2, S2, cd1, aR, aI, 0);
        // 1-level pre-reduce: lane L holds v[L] + v[L+16] for L < 16
        aR = f2add(aR, __shfl_down_sync(0xFFFFFFFFu, aR, 16));
        aI = f2add(aI, __shfl_down_sync(0xFFFFFFFFu, aI, 16));
        if (lane < 16) {
            sRbuf[st * ROWW + slot] = aR;
            sIbuf[st * ROWW + slot] = aI;
        }
        if (st < CHUNK - 1) {
            ROT(T0, C0, S0, CW0, SW0, YS0);
            ROT(T1, C1, S1, CW1, SW1, YS1);
            ROT(T2, C2, S2, CW2, SW2, YS2);
        }
    }
    __syncthreads();

    // ---- final reduction: 128 partials per (step, kx-slot) ----
    const float SCALE = (float)(-16384.0 / (4.0 * 3.14159265358979323846
                                                * 3.14159265358979323846));
    for (int st = wid; st < CHUNK; st += 8) {
        int fy = ky0 + st;
        if (fy >= FY2) continue;               // tail rows of last chunk
        const u64* rR = &sRbuf[st * ROWW];
        const u64* rI = &sIbuf[st * ROWW];
        u64 aR = f2add(f2add(rR[lane],      rR[lane + 32]),
                       f2add(rR[lane + 64], rR[lane + 96]));
        u64 aI = f2add(f2add(rI[lane],      rI[lane + 32]),
                       f2add(rI[lane + 64], rI[lane + 96]));
#pragma unroll
        for (int off = 16; off > 0; off >>= 1) {
            aR = f2add(aR, __shfl_down_sync(0xFFFFFFFFu, aR, off));
            aI = f2add(aI, __shfl_down_sync(0xFFFFFFFFu, aI, off));
        }
        if (lane == 0) {
            float Rl, Rh, Il, Ih;
            upk(aR, Rl, Rh); upk(aI, Il, Ih);
            float oRl =  SCALE * Rl, oRh =  SCALE * Rh;
            float oIl = -SCALE * Il, oIh = -SCALE * Ih;   // aI held -Im
            if (kxp == 0 && fy == 0) {
                // DC: F[:,0,0,:,:] = 8192*sum(C*D) in BOTH re and im
                // (lo half held junk from the sanitized rcp; overwritten here)
                float ssum = 0.0f;
                for (int e = 0; e < NEE; ++e) ssum += scd[e];
                oRl = 8192.0f * ssum;
                oIl = oRl;
            }
            int base = ((b * FXX + fx0) * FY2 + fy) * 2;
            out[base + 0] = oRl;
            out[base + 1] = oIl;
            out[base + 2 * FY2 + 0] = oRh;   // fx0 + 1
            out[base + 2 * FY2 + 1] = oIh;
        }
    }
}

extern "C" void kernel_launch(void* const* d_in, const int* in_sizes, int n_in,
                              void* d_out, int out_size)
{
    const float* V = (const float*)d_in[0];
    const int*   E = (const int*)  d_in[1];
    const float* D = (const float*)d_in[2];
    float* out = (float*)d_out;

    const int B = in_sizes[0] / (NVV * 2);   // 2
    cudaFuncSetAttribute(ddsl_spec_kernel,
                         cudaFuncAttributeMaxDynamicSharedMemorySize, SMEM_BYTES);
    dim3 grid(KXP, NCHUNK, B);               // (64, 4, 2) = 512 blocks
    ddsl_spec_kernel<<<grid, BLOCK, SMEM_BYTES>>>(V, E, D, out);
}

// round 11
// speedup vs baseline: 1.1404x; 1.1339x over previous
#include <cuda_runtime.h>
#include <math.h>

// DDSL spec: B=2, NV=NE=512, RES=(128,128) -> freq grid 128 x 65, J=2.
// Direct packed kernel: two adjacent fx freqs (kx,kx+1) per thread via f32x2.
// Each lane owns a 32-edge chunk split into TWO independent 16-edge ring
// chains (ILP). Ring reuse: t1(edge e) = t0(edge e+1) -> 1 vertex sincos per
// edge. Divide via single product-reciprocal (dlo sanitized; junk lands only
// in the k=(0,0) slot which DC overwrites).

#define NV      512
#define NE      512
#define FX      128
#define FY2     65
#define NFP     (FX / 2 * FY2)      // 4160 fx-pairs
#define LANES   16                  // edge-chunk lanes per freq-pair
#define GROUPS  16                  // freq-pairs per block
#define BLOCK   256
#define EPL     16                  // edges per chain (2 chains per lane)
#define PADDED  529                 // pad(e)=e+(e>>5); pad(512)=528 wrap dup

typedef unsigned long long u64;

__device__ __forceinline__ u64 pk2(float a, float b) {
    u64 r; asm("mov.b64 %0, {%1, %2};" : "=l"(r) : "f"(a), "f"(b)); return r;
}
__device__ __forceinline__ void upk(u64 v, float& a, float& b) {
    asm("mov.b64 {%0, %1}, %2;" : "=f"(a), "=f"(b) : "l"(v));
}
__device__ __forceinline__ u64 f2fma(u64 a, u64 b, u64 c) {
    u64 d; asm("fma.rn.f32x2 %0, %1, %2, %3;" : "=l"(d) : "l"(a), "l"(b), "l"(c)); return d;
}
__device__ __forceinline__ u64 f2add(u64 a, u64 b) {
    u64 d; asm("add.rn.f32x2 %0, %1, %2;" : "=l"(d) : "l"(a), "l"(b)); return d;
}
__device__ __forceinline__ u64 f2mul(u64 a, u64 b) {
    u64 d; asm("mul.rn.f32x2 %0, %1, %2;" : "=l"(d) : "l"(a), "l"(b)); return d;
}

__device__ __forceinline__ float fracr(float t) {
    const float MAGIC = 12582912.0f;  // 1.5 * 2^23
    float g = __fadd_rn(t, MAGIC);
    float r = __fadd_rn(g, -MAGIC);
    return t - r;
}

__global__ __launch_bounds__(BLOCK, 4)
void ddsl_spec_kernel(const float* __restrict__ V,
                      const int*   __restrict__ E,
                      const float* __restrict__ D,
                      float*       __restrict__ out)
{
    __shared__ float sX[PADDED];
    __shared__ float sY[PADDED];
    __shared__ float sCD[PADDED];

    const int b = blockIdx.y;

    // ---- stage ring vertices + C*D ----
    for (int e = threadIdx.x; e < NE; e += BLOCK) {
        int i0 = E[(b * NE + e) * 2 + 0];
        int i1 = E[(b * NE + e) * 2 + 1];
        float ax = V[(b * NV + i0) * 2 + 0];
        float ay = V[(b * NV + i0) * 2 + 1];
        float bx = V[(b * NV + i1) * 2 + 0];
        float by = V[(b * NV + i1) * 2 + 1];
        int p = e + (e >> 5);
        sX[p] = ax;
        sY[p] = ay;
        sCD[p] = (ax * by - ay * bx) * D[b * NE + e];
        if (e == 0) { sX[528] = ax; sY[528] = ay; }   // ring wrap dup
    }
    __syncthreads();

    const int lane = threadIdx.x & (LANES - 1);
    const int fp   = blockIdx.x * GROUPS + (threadIdx.x >> 4);

    const int fxp = fp / FY2;
    const int fy  = fp - fxp * FY2;
    const int fx0 = 2 * fxp;
    const int kx0 = (fx0 < FX / 2) ? fx0 : fx0 - FX;   // kx1 = kx0 + 1
    const float fkx = (float)kx0;
    const float fky = (float)fy;

    const float TWO_PI = 6.28318530717958647692f;
    const float MAGIC  = 12582912.0f;
    const u64 MAGIC2  = pk2(MAGIC, MAGIC);
    const u64 NMAGIC2 = pk2(-MAGIC, -MAGIC);
    const u64 NEG1    = pk2(-1.0f, -1.0f);
    const u64 TWOPI2  = pk2(TWO_PI, TWO_PI);

    // lane's 32-edge pad-group: pad(32*lane + i) = 33*lane + i, i = 0..31;
    // next group starts at offset 33 (offset 32 is the pad hole).
    const float* xb = &sX[33 * lane];
    const float* yb = &sY[33 * lane];
    const float* cb = &sCD[33 * lane];

    // init vertex (t, cos, sin) packed over (kx, kx+1) at shared offset OFS
#define INITV(OFS, T, C, S)                                                \
    {                                                                      \
        float vx = xb[OFS], vy = yb[OFS];                                  \
        float tl = fmaf(vy, fky, vx * fkx);                                \
        float th = tl + vx;                                                \
        float sl, cl, sh, chh;                                             \
        __sincosf(fracr(tl) * TWO_PI, &sl, &cl);                           \
        __sincosf(fracr(th) * TWO_PI, &sh, &chh);                          \
        T = pk2(tl, th); C = pk2(cl, chh); S = pk2(sl, sh);                \
    }

    // advance chain by one edge: new vertex at OFS, edge weight CD
#define STEP(T, C, S, OFS, CD, AR, AI)                                     \
    {                                                                      \
        float nx = xb[OFS], ny = yb[OFS];                                  \
        float cd = CD;                                                     \
        float t1lo = fmaf(ny, fky, nx * fkx);                              \
        u64 T1 = pk2(t1lo, t1lo + nx);                                     \
        u64 g  = f2add(T1, MAGIC2);                                        \
        u64 rr = f2add(g, NMAGIC2);                                        \
        u64 uu = f2fma(rr, NEG1, T1);                                      \
        u64 ph = f2mul(uu, TWOPI2);                                        \
        float plo, phi_, sl, cl, sh, chh;                                  \
        upk(ph, plo, phi_);                                                \
        __sincosf(plo, &sl, &cl);                                          \
        __sincosf(phi_, &sh, &chh);                                        \
        u64 SN1 = pk2(sl, sh), CS1 = pk2(cl, chh);                         \
        u64 dt  = f2fma(T1, NEG1, T);                                      \
        u64 den = f2mul(f2mul(T, T1), dt);                                 \
        u64 nt  = f2mul(T, NEG1);                                          \
        u64 nr  = f2fma(CS1, nt, f2fma(C, T1, dt));                        \
        u64 ni  = f2fma(SN1, nt, f2mul(S, T1));                            \
        float dlo, dhi; upk(den, dlo, dhi);                                \
        dlo = (dlo == 0.0f) ? 1.0f : dlo;                                  \
        float rp = __fdividef(cd, dlo * dhi);                              \
        u64 rc = pk2(rp * dhi, rp * dlo);                                  \
        AR = f2fma(nr, rc, AR);                                            \
        AI = f2fma(ni, rc, AI);                                            \
        T = T1; C = CS1; S = SN1;                                          \
    }

    u64 aR0 = pk2(0.0f, 0.0f), aI0 = pk2(0.0f, 0.0f);
    u64 aR1 = pk2(0.0f, 0.0f), aI1 = pk2(0.0f, 0.0f);

    u64 TA, CA, SA, TB, CB, SB;
    INITV(0,  TA, CA, SA);     // chain A: edges 0..15 of chunk
    INITV(16, TB, CB, SB);     // chain B: edges 16..31 of chunk

#pragma unroll
    for (int i = 0; i < EPL; ++i) {
        const int offA = i + 1;                        // 1..16
        const int offB = (i == EPL - 1) ? 33 : 17 + i; // 17..31, then 33 (wrap)
        STEP(TA, CA, SA, offA, cb[i],      aR0, aI0);
        STEP(TB, CB, SB, offB, cb[16 + i], aR1, aI1);
    }

    u64 accR = f2add(aR0, aR1);
    u64 accI = f2add(aI0, aI1);   // holds -Im

    // ---- reduce the 16 edge-chunk lanes (packed) ----
#pragma unroll
    for (int off = LANES / 2; off > 0; off >>= 1) {
        accR = f2add(accR, __shfl_down_sync(0xFFFFFFFFu, accR, off, LANES));
        accI = f2add(accI, __shfl_down_sync(0xFFFFFFFFu, accI, off, LANES));
    }

    if (lane == 0) {
        // F = -einsum * RES^J ; (2*pi)^-2 folded into SCALE. accI = -Im.
        const float SCALE = (float)(-16384.0 / (4.0 * 3.14159265358979323846
                                                    * 3.14159265358979323846));
        float aRlo, aRhi, aIlo, aIhi;
        upk(accR, aRlo, aRhi);
        upk(accI, aIlo, aIhi);
        float oRlo =  SCALE * aRlo, oRhi =  SCALE * aRhi;
        float oIlo = -SCALE * aIlo, oIhi = -SCALE * aIhi;

        if (fp == 0) {
            // DC: F[:,0,0,:,:] = 8192*sum(C*D) in BOTH re and im
            float s = 0.0f;
#pragma unroll 8
            for (int e = 0; e < NE; ++e) s += sCD[e + (e >> 5)];
            oRlo = 8192.0f * s;
            oIlo = oRlo;
        }

        int base = ((b * FX + fx0) * FY2 + fy) * 2;
        out[base + 0] = oRlo;
        out[base + 1] = oIlo;
        out[base + 2 * FY2 + 0] = oRhi;   // fx0 + 1
        out[base + 2 * FY2 + 1] = oIhi;
    }
}

extern "C" void kernel_launch(void* const* d_in, const int* in_sizes, int n_in,
                              void* d_out, int out_size)
{
    const float* V = (const float*)d_in[0];
    const int*   E = (const int*)  d_in[1];
    const float* D = (const float*)d_in[2];
    float* out = (float*)d_out;

    const int B = in_sizes[0] / (NV * 2);   // 2
    dim3 grid(NFP / GROUPS, B);             // (260, 2) = 520 blocks
    ddsl_spec_kernel<<<grid, BLOCK>>>(V, E, D, out);
}